// round 16
// baseline (speedup 1.0000x reference)
#include <cuda_runtime.h>
#include <cuda_bf16.h>
#include <cuda_fp16.h>
#include <math.h>
#include <stdint.h>

#define DIM    768
#define DEPTH  6
#define HEADS  12
#define DHEAD  64
#define INNER  768
#define MLPD   3072
#define BATCH  4
#define SEQ    2048
#define TOK    (BATCH*SEQ)      /* 8192 */
#define QKVD   (3*INNER)        /* 2304 */
#define QSCALE 0.18033688011112042f   /* 0.125 * log2(e) */

// ---------------- scratch (device globals; no allocations) ----------------
__device__ float  g_x   [(size_t)TOK*DIM];    // residual stream fp32
__device__ __half g_qkv16[(size_t)TOK*QKVD];  // fused qkv fp16 (Q pre-scaled)
__device__ __half g_ln16[(size_t)TOK*DIM];    // LN output fp16
__device__ __half g_ct16[(size_t)TOK*DIM];    // attention ctx fp16
__device__ __half g_h16 [(size_t)TOK*MLPD];   // mlp hidden fp16
// transposed fp16 weights [layer][N][K]
__device__ __half g_wqkvt[(size_t)DEPTH*QKVD*DIM];
__device__ __half g_woutt[(size_t)DEPTH*DIM*INNER];
__device__ __half g_w1t  [(size_t)DEPTH*MLPD*DIM];
__device__ __half g_w2t  [(size_t)DEPTH*DIM*MLPD];

// ====================== PTX helpers =======================================
__device__ __forceinline__ uint32_t smem_u32(const void* p){
    uint32_t a;
    asm("{ .reg .u64 t; cvta.to.shared.u64 t, %1; cvt.u32.u64 %0, t; }"
        : "=r"(a) : "l"(p));
    return a;
}
__device__ __forceinline__ void cp16(uint32_t s, const void* g){
    asm volatile("cp.async.cg.shared.global [%0], [%1], 16;" :: "r"(s), "l"(g));
}
#define CP_COMMIT() asm volatile("cp.async.commit_group;" ::: "memory")
#define CP_WAIT1()  asm volatile("cp.async.wait_group 1;" ::: "memory")
#define CP_WAIT0()  asm volatile("cp.async.wait_group 0;" ::: "memory")

__device__ __forceinline__ void ldmx4(uint32_t addr, uint32_t& r0, uint32_t& r1,
                                      uint32_t& r2, uint32_t& r3){
    asm volatile("ldmatrix.sync.aligned.m8n8.x4.shared.b16 {%0,%1,%2,%3}, [%4];"
        : "=r"(r0), "=r"(r1), "=r"(r2), "=r"(r3) : "r"(addr));
}
__device__ __forceinline__ void ldmx4t(uint32_t addr, uint32_t& r0, uint32_t& r1,
                                       uint32_t& r2, uint32_t& r3){
    asm volatile("ldmatrix.sync.aligned.m8n8.x4.trans.shared.b16 {%0,%1,%2,%3}, [%4];"
        : "=r"(r0), "=r"(r1), "=r"(r2), "=r"(r3) : "r"(addr));
}
// fp16 mma
__device__ __forceinline__ void mma16816h(float* c, const uint32_t* a,
                                          uint32_t b0, uint32_t b1){
    asm volatile(
        "mma.sync.aligned.m16n8k16.row.col.f32.f16.f16.f32 "
        "{%0,%1,%2,%3}, {%4,%5,%6,%7}, {%8,%9}, {%0,%1,%2,%3};"
        : "+f"(c[0]), "+f"(c[1]), "+f"(c[2]), "+f"(c[3])
        : "r"(a[0]), "r"(a[1]), "r"(a[2]), "r"(a[3]), "r"(b0), "r"(b1));
}
// FMA-pipe exp2; degree-6 (accurate)
__device__ __forceinline__ float exp2_fast(float t){
    t = fmaxf(t, -120.f);
    float n = rintf(t);
    float f = t - n;
    float p = 1.5403530e-4f;
    p = fmaf(p, f, 1.3333558e-3f);
    p = fmaf(p, f, 9.6181291e-3f);
    p = fmaf(p, f, 5.5504109e-2f);
    p = fmaf(p, f, 2.4022651e-1f);
    p = fmaf(p, f, 6.9314718e-1f);
    p = fmaf(p, f, 1.0f);
    return __int_as_float(__float_as_int(p) + (((int)n) << 23));
}
// degree-4 exp2 for softmax probabilities (rel err ~4e-5)
__device__ __forceinline__ float exp2_p4(float t){
    t = fmaxf(t, -120.f);
    float n = rintf(t);
    float f = t - n;
    float p = 9.6181291e-3f;
    p = fmaf(p, f, 5.5504109e-2f);
    p = fmaf(p, f, 2.4022651e-1f);
    p = fmaf(p, f, 6.9314718e-1f);
    p = fmaf(p, f, 1.0f);
    return __int_as_float(__float_as_int(p) + (((int)n) << 23));
}
// GELU via A&S 7.1.26 erf approximation (abs err <= 1.5e-7), FMA+rcp only.
__device__ __forceinline__ float gelu_fast(float x){
    const float z  = fabsf(x) * 0.70710678118654752f;   // |x|/sqrt(2)
    const float t  = __frcp_rn(fmaf(0.3275911f, z, 1.f));
    float p = 1.061405429f;
    p = fmaf(p, t, -1.453152027f);
    p = fmaf(p, t,  1.421413741f);
    p = fmaf(p, t, -0.284496736f);
    p = fmaf(p, t,  0.254829592f);
    // e^{-z^2} = 2^{-z^2 * log2(e)}
    const float e  = exp2_fast(-z * z * 1.4426950408889634f);
    const float er = fmaf(-p * t, e, 1.f);               // erf(|x|/sqrt2)
    const float sg = (x >= 0.f) ? er : -er;
    return 0.5f * x * (1.f + sg);
}

// ====================== weight transpose to fp16 ===========================
__global__ void transpose_cvt(const float* __restrict__ W,
                              __half* __restrict__ Wh, int K, int N)
{
    __shared__ float tile[32][33];
    const size_t off = (size_t)blockIdx.z * K * N;
    const int n0 = blockIdx.x * 32, k0 = blockIdx.y * 32;
    const int tx = threadIdx.x, ty = threadIdx.y;
#pragma unroll
    for (int i = 0; i < 32; i += 8)
        tile[ty + i][tx] = W[off + (size_t)(k0 + ty + i) * N + n0 + tx];
    __syncthreads();
#pragma unroll
    for (int i = 0; i < 32; i += 8) {
        size_t oidx = off + (size_t)(n0 + ty + i) * K + k0 + tx;
        Wh[oidx] = __float2half_rn(tile[tx][ty + i]);
    }
}

// ====================== LayerNorm: 1 warp / token, 8 tokens / block ========
template<bool HOUT>
__global__ void ln_kernel(const float* __restrict__ x, const float* __restrict__ g,
                          const float* __restrict__ b, float* __restrict__ y,
                          __half* __restrict__ yh)
{
    const int warp = threadIdx.x >> 5, lane = threadIdx.x & 31;
    const int t = blockIdx.x * 8 + warp;
    const float* xp = x + (size_t)t * DIM;

    float v[24];
    float s1 = 0.f, s2 = 0.f;
#pragma unroll
    for (int i = 0; i < 6; i++) {
        float4 f = *reinterpret_cast<const float4*>(xp + i * 128 + lane * 4);
        v[i*4+0] = f.x; v[i*4+1] = f.y; v[i*4+2] = f.z; v[i*4+3] = f.w;
        s1 += f.x + f.y + f.z + f.w;
        s2 += f.x*f.x + f.y*f.y + f.z*f.z + f.w*f.w;
    }
#pragma unroll
    for (int o = 16; o > 0; o >>= 1) {
        s1 += __shfl_xor_sync(0xffffffffu, s1, o);
        s2 += __shfl_xor_sync(0xffffffffu, s2, o);
    }
    const float mu  = s1 * (1.f / DIM);
    const float var = s2 * (1.f / DIM) - mu * mu;
    const float rs  = rsqrtf(var + 1e-5f);

#pragma unroll
    for (int i = 0; i < 6; i++) {
        const int d = i * 128 + lane * 4;
        float4 gg = *reinterpret_cast<const float4*>(g + d);
        float4 bb = *reinterpret_cast<const float4*>(b + d);
        float y0 = (v[i*4+0] - mu) * rs * gg.x + bb.x;
        float y1 = (v[i*4+1] - mu) * rs * gg.y + bb.y;
        float y2 = (v[i*4+2] - mu) * rs * gg.z + bb.z;
        float y3 = (v[i*4+3] - mu) * rs * gg.w + bb.w;
        if (HOUT) {
            uint2 pk;
            __half h0 = __float2half_rn(y0), h1 = __float2half_rn(y1);
            __half h2 = __float2half_rn(y2), h3 = __float2half_rn(y3);
            pk.x = (uint32_t)__half_as_ushort(h0) | ((uint32_t)__half_as_ushort(h1) << 16);
            pk.y = (uint32_t)__half_as_ushort(h2) | ((uint32_t)__half_as_ushort(h3) << 16);
            *reinterpret_cast<uint2*>(yh + (size_t)t * DIM + d) = pk;
        } else {
            *reinterpret_cast<float4*>(y + (size_t)t * DIM + d) =
                make_float4(y0, y1, y2, y3);
        }
    }
}

// ====================== fp16 1-product GEMM (BK=64, 3-stage, 2 CTAs/SM) ====
// Split-K via gridDim.z.  EPI: 0 = qkv out; 1 = +bias,gelu,fp16;
// 2 = +bias(z0) atomic += xres; 3 = atomic += xres.
#define STAGE_SZ 32768u
template<int EPI>
__global__ void __launch_bounds__(256, 2)
gemm_mma(const __half* __restrict__ Ah, const __half* __restrict__ Bh,
         const float* __restrict__ bias, float* __restrict__ xres,
         __half* __restrict__ Ch, int M, int N, int K)
{
    extern __shared__ char smem[];
    const uint32_t sb0 = smem_u32(smem);
    const int tid  = threadIdx.x;
    const int lane = tid & 31, warp = tid >> 5;
    const int wm = warp >> 1, wn = warp & 1;
    const int bn = blockIdx.x, bm = blockIdx.y;
    const int ksp   = K / (int)gridDim.z;
    const int kbase = blockIdx.z * ksp;
    const int nkt   = ksp >> 6;

    auto load_stage = [&](int kt, int st){
        const uint32_t base = sb0 + (uint32_t)st * STAGE_SZ;
        const size_t kof = (size_t)kbase + (size_t)kt * 64;
#pragma unroll
        for (int i = 0; i < 4; i++) {
            const int idx = tid + i * 256;
            const int row = idx >> 3, c = idx & 7;
            const uint32_t so = (uint32_t)(row * 128 + ((c ^ (row & 7)) << 4));
            const size_t ga = (size_t)(bm * 128 + row) * K + kof + c * 8;
            const size_t gb = (size_t)(bn * 128 + row) * K + kof + c * 8;
            cp16(base + so,          Ah + ga);
            cp16(base + 16384u + so, Bh + gb);
        }
    };

    float acc[2][8][4];
#pragma unroll
    for (int mt = 0; mt < 2; mt++)
#pragma unroll
        for (int nt = 0; nt < 8; nt++)
#pragma unroll
            for (int q = 0; q < 4; q++) acc[mt][nt][q] = 0.f;

    load_stage(0, 0); CP_COMMIT();
    load_stage(1, 1); CP_COMMIT();

    const int arow = wm * 32 + (lane & 15);
    const int acs  = lane >> 4;
    const int brow = wn * 64 + (lane & 7) + ((lane >> 4) << 3);
    const int bcs  = (lane >> 3) & 1;

    for (int kt = 0; kt < nkt; kt++) {
        if (kt == nkt - 1) { CP_WAIT0(); } else { CP_WAIT1(); }
        __syncthreads();
        if (kt + 2 < nkt) { load_stage(kt + 2, (kt + 2) % 3); CP_COMMIT(); }

        const uint32_t base = sb0 + (uint32_t)(kt % 3) * STAGE_SZ;
#pragma unroll
        for (int ks = 0; ks < 4; ks++) {
            uint32_t ah[2][4];
#pragma unroll
            for (int mt = 0; mt < 2; mt++) {
                const int r = arow + mt * 16;
                const int c = ks * 2 + acs;
                const uint32_t off = (uint32_t)(r * 128 + ((c ^ (r & 7)) << 4));
                ldmx4(base + off, ah[mt][0], ah[mt][1], ah[mt][2], ah[mt][3]);
            }
#pragma unroll
            for (int bt = 0; bt < 4; bt++) {
                const int r = brow + bt * 16;
                const int c = ks * 2 + bcs;
                const uint32_t off = (uint32_t)(r * 128 + ((c ^ (r & 7)) << 4));
                uint32_t bh[4];
                ldmx4(base + 16384u + off, bh[0], bh[1], bh[2], bh[3]);
#pragma unroll
                for (int mt = 0; mt < 2; mt++) {
                    mma16816h(acc[mt][2*bt],   ah[mt], bh[0], bh[1]);
                    mma16816h(acc[mt][2*bt+1], ah[mt], bh[2], bh[3]);
                }
            }
        }
        __syncthreads();
    }

    const int rbase = bm * 128 + wm * 32 + (lane >> 2);
    const int cbase = bn * 128 + wn * 64 + (lane & 3) * 2;
    const bool z0 = (blockIdx.z == 0);
#pragma unroll
    for (int mt = 0; mt < 2; mt++) {
#pragma unroll
        for (int nt = 0; nt < 8; nt++) {
            const int gcol = cbase + nt * 8;
#pragma unroll
            for (int h = 0; h < 2; h++) {
                const int grow = rbase + mt * 16 + h * 8;
                float v0 = acc[mt][nt][2*h], v1 = acc[mt][nt][2*h+1];
                const size_t oidx = (size_t)grow * N + gcol;
                if (EPI == 0 || EPI == 1) {
                    if (EPI == 0) {
                        const float sc = (gcol < INNER) ? QSCALE : 1.f;
                        v0 *= sc; v1 *= sc;
                    } else {
                        v0 = gelu_fast(v0 + bias[gcol]);
                        v1 = gelu_fast(v1 + bias[gcol + 1]);
                    }
                    __half h0 = __float2half_rn(v0), h1 = __float2half_rn(v1);
                    *reinterpret_cast<uint32_t*>(Ch + oidx) =
                        (uint32_t)__half_as_ushort(h0) |
                        ((uint32_t)__half_as_ushort(h1) << 16);
                } else {
                    if (EPI == 2 && z0) { v0 += bias[gcol]; v1 += bias[gcol + 1]; }
                    atomicAdd(xres + oidx,     v0);
                    atomicAdd(xres + oidx + 1, v1);
                }
            }
        }
    }
}

// ====================== fp16 1-product flash attention (2 CTAs/SM) =========
// grid (SEQ/128, HEADS, BATCH), 256 threads (8 warps x 16 query rows).
#define ATTN_SMEM (16384 + 2*16384)
__global__ void __launch_bounds__(256, 2)
attn_mma(const __half* __restrict__ qkv, __half* __restrict__ ctx)
{
    extern __shared__ char smem[];
    const uint32_t sb = smem_u32(smem);
    const uint32_t QS = sb;
    const int tid = threadIdx.x, lane = tid & 31, wid = tid >> 5;
    const int b = blockIdx.z, h = blockIdx.y, qt = blockIdx.x;
    const int tok0 = b * SEQ + qt * 128;

#pragma unroll
    for (int i = 0; i < 4; i++) {
        const int idx = tid + i * 256;
        const int row = idx >> 3, c = idx & 7;
        const uint32_t so = (uint32_t)(row * 128 + ((c ^ (row & 7)) << 4));
        cp16(QS + so, qkv + (size_t)(tok0 + row) * QKVD + h * DHEAD + c * 8);
    }

    auto load_kv = [&](int t, int st){
        const uint32_t base = sb + 16384u + (uint32_t)st * 16384u;
        const int kv0 = b * SEQ + t * 64;
#pragma unroll
        for (int i = 0; i < 2; i++) {
            const int idx = tid + i * 256;
            const int row = idx >> 3, c = idx & 7;
            const uint32_t so = (uint32_t)(row * 128 + ((c ^ (row & 7)) << 4));
            const size_t gk = (size_t)(kv0 + row) * QKVD + INNER + h * DHEAD + c * 8;
            const size_t gv = (size_t)(kv0 + row) * QKVD + 2 * INNER + h * DHEAD + c * 8;
            cp16(base + so,         qkv + gk);
            cp16(base + 8192u + so, qkv + gv);
        }
    };
    load_kv(0, 0); CP_COMMIT();

    float O[8][4];
#pragma unroll
    for (int nt = 0; nt < 8; nt++)
#pragma unroll
        for (int q = 0; q < 4; q++) O[nt][q] = 0.f;
    float m0 = -1e30f, m1 = -1e30f, l0 = 0.f, l1 = 0.f;
    const int m0row = wid * 16;

    const int NT = SEQ / 64;
    for (int t = 0; t < NT; t++) {
        if (t + 1 < NT) { load_kv(t + 1, (t + 1) & 1); CP_COMMIT(); CP_WAIT1(); }
        else            { CP_WAIT0(); }
        __syncthreads();
        const uint32_t kb = sb + 16384u + (uint32_t)(t & 1) * 16384u;

        float S[8][4];
#pragma unroll
        for (int nt = 0; nt < 8; nt++)
#pragma unroll
            for (int q = 0; q < 4; q++) S[nt][q] = 0.f;
#pragma unroll
        for (int ks = 0; ks < 4; ks++) {
            uint32_t qf[4];
            {
                const int r = m0row + (lane & 15);
                const int c = ks * 2 + (lane >> 4);
                const uint32_t off = (uint32_t)(r * 128 + ((c ^ (r & 7)) << 4));
                ldmx4(QS + off, qf[0], qf[1], qf[2], qf[3]);
            }
#pragma unroll
            for (int bt = 0; bt < 4; bt++) {
                const int r = bt * 16 + (lane & 7) + ((lane >> 4) << 3);
                const int c = ks * 2 + ((lane >> 3) & 1);
                const uint32_t off = (uint32_t)(r * 128 + ((c ^ (r & 7)) << 4));
                uint32_t kh[4];
                ldmx4(kb + off, kh[0], kh[1], kh[2], kh[3]);
                mma16816h(S[2*bt],   qf, kh[0], kh[1]);
                mma16816h(S[2*bt+1], qf, kh[2], kh[3]);
            }
        }

        // ---- online softmax with skip-rescale ----
        float mt0 = -1e30f, mt1 = -1e30f;
#pragma unroll
        for (int nt = 0; nt < 8; nt++) {
            mt0 = fmaxf(mt0, fmaxf(S[nt][0], S[nt][1]));
            mt1 = fmaxf(mt1, fmaxf(S[nt][2], S[nt][3]));
        }
        mt0 = fmaxf(mt0, __shfl_xor_sync(0xffffffffu, mt0, 1));
        mt0 = fmaxf(mt0, __shfl_xor_sync(0xffffffffu, mt0, 2));
        mt1 = fmaxf(mt1, __shfl_xor_sync(0xffffffffu, mt1, 1));
        mt1 = fmaxf(mt1, __shfl_xor_sync(0xffffffffu, mt1, 2));

        const bool chg = __any_sync(0xffffffffu, (mt0 > m0) | (mt1 > m1));
        if (chg) {
            const float mn0 = fmaxf(m0, mt0), mn1 = fmaxf(m1, mt1);
            const float cr0 = exp2_fast(m0 - mn0), cr1 = exp2_fast(m1 - mn1);
            m0 = mn0; m1 = mn1;
            l0 *= cr0; l1 *= cr1;
#pragma unroll
            for (int nt = 0; nt < 8; nt++) {
                O[nt][0] *= cr0; O[nt][1] *= cr0;
                O[nt][2] *= cr1; O[nt][3] *= cr1;
            }
        }

        uint32_t phi[4][4];
        float s0 = 0.f, s1 = 0.f;
#pragma unroll
        for (int nt = 0; nt < 8; nt++) {
            float p0 = exp2_p4(S[nt][0] - m0);
            float p1 = exp2_p4(S[nt][1] - m0);
            float p2 = exp2_p4(S[nt][2] - m1);
            float p3 = exp2_p4(S[nt][3] - m1);
            s0 += p0 + p1; s1 += p2 + p3;
            __half h0 = __float2half_rn(p0), h1 = __float2half_rn(p1);
            __half h2 = __float2half_rn(p2), h3 = __float2half_rn(p3);
            const int t2 = nt >> 1, o = (nt & 1) * 2;
            phi[t2][o] = (uint32_t)__half_as_ushort(h0) |
                         ((uint32_t)__half_as_ushort(h1) << 16);
            phi[t2][o+1] = (uint32_t)__half_as_ushort(h2) |
                           ((uint32_t)__half_as_ushort(h3) << 16);
        }
        s0 += __shfl_xor_sync(0xffffffffu, s0, 1);
        s0 += __shfl_xor_sync(0xffffffffu, s0, 2);
        s1 += __shfl_xor_sync(0xffffffffu, s1, 1);
        s1 += __shfl_xor_sync(0xffffffffu, s1, 2);
        l0 += s0;
        l1 += s1;

#pragma unroll
        for (int t2 = 0; t2 < 4; t2++) {
#pragma unroll
            for (int dn = 0; dn < 4; dn++) {
                const int r = t2 * 16 + (lane & 15);
                const int c = dn * 2 + (lane >> 4);
                const uint32_t off = (uint32_t)(r * 128 + ((c ^ (r & 7)) << 4));
                uint32_t vh[4];
                ldmx4t(kb + 8192u + off, vh[0], vh[1], vh[2], vh[3]);
                mma16816h(O[2*dn],   phi[t2], vh[0], vh[1]);
                mma16816h(O[2*dn+1], phi[t2], vh[2], vh[3]);
            }
        }
        __syncthreads();
    }

    const float i0 = 1.f / l0, i1 = 1.f / l1;
    const int r0 = tok0 + m0row + (lane >> 2);
#pragma unroll
    for (int nt = 0; nt < 8; nt++) {
        const int col = h * DHEAD + nt * 8 + (lane & 3) * 2;
#pragma unroll
        for (int hh = 0; hh < 2; hh++) {
            const float inv = hh ? i1 : i0;
            float v0 = O[nt][2*hh] * inv, v1 = O[nt][2*hh+1] * inv;
            __half h0 = __float2half_rn(v0), h1 = __float2half_rn(v1);
            const size_t oidx = (size_t)(r0 + hh * 8) * DIM + col;
            *reinterpret_cast<uint32_t*>(ctx + oidx) =
                (uint32_t)__half_as_ushort(h0) |
                ((uint32_t)__half_as_ushort(h1) << 16);
        }
    }
}

// ====================== driver =============================================
#define GEMM_SMEM (3 * 32768)

extern "C" void kernel_launch(void* const* d_in, const int* in_sizes, int n_in,
                              void* d_out, int out_size)
{
    const float* x    = (const float*)d_in[0];
    const float* ln1g = (const float*)d_in[1];
    const float* ln1b = (const float*)d_in[2];
    const float* wqkv = (const float*)d_in[3];
    const float* wout = (const float*)d_in[4];
    const float* ln2g = (const float*)d_in[5];
    const float* ln2b = (const float*)d_in[6];
    const float* w1   = (const float*)d_in[7];
    const float* b1   = (const float*)d_in[8];
    const float* w2   = (const float*)d_in[9];
    const float* b2   = (const float*)d_in[10];
    const float* fng  = (const float*)d_in[11];
    const float* fnb  = (const float*)d_in[12];

    float *px;
    __half *pqkv, *pln16, *pct16, *ph16;
    __half *qkvt, *outt, *w1t, *w2t;
    cudaGetSymbolAddress((void**)&px,    g_x);
    cudaGetSymbolAddress((void**)&pqkv,  g_qkv16);
    cudaGetSymbolAddress((void**)&pln16, g_ln16);
    cudaGetSymbolAddress((void**)&pct16, g_ct16);
    cudaGetSymbolAddress((void**)&ph16,  g_h16);
    cudaGetSymbolAddress((void**)&qkvt,  g_wqkvt);
    cudaGetSymbolAddress((void**)&outt,  g_woutt);
    cudaGetSymbolAddress((void**)&w1t,   g_w1t);
    cudaGetSymbolAddress((void**)&w2t,   g_w2t);

    cudaFuncSetAttribute(gemm_mma<0>, cudaFuncAttributeMaxDynamicSharedMemorySize, GEMM_SMEM);
    cudaFuncSetAttribute(gemm_mma<1>, cudaFuncAttributeMaxDynamicSharedMemorySize, GEMM_SMEM);
    cudaFuncSetAttribute(gemm_mma<2>, cudaFuncAttributeMaxDynamicSharedMemorySize, GEMM_SMEM);
    cudaFuncSetAttribute(gemm_mma<3>, cudaFuncAttributeMaxDynamicSharedMemorySize, GEMM_SMEM);
    cudaFuncSetAttribute(attn_mma, cudaFuncAttributeMaxDynamicSharedMemorySize, ATTN_SMEM);

    {
        dim3 tblk(32, 8);
        transpose_cvt<<<dim3(QKVD/32, DIM/32, DEPTH), tblk>>>(wqkv, qkvt, DIM, QKVD);
        transpose_cvt<<<dim3(DIM/32, INNER/32, DEPTH), tblk>>>(wout, outt, INNER, DIM);
        transpose_cvt<<<dim3(MLPD/32, DIM/32, DEPTH), tblk>>>(w1, w1t, DIM, MLPD);
        transpose_cvt<<<dim3(DIM/32, MLPD/32, DEPTH), tblk>>>(w2, w2t, MLPD, DIM);
    }

    cudaMemcpyAsync(px, x, sizeof(float) * (size_t)TOK * DIM,
                    cudaMemcpyDeviceToDevice, 0);

    const dim3 blk256(256);
    for (int i = 0; i < DEPTH; i++) {
        ln_kernel<true><<<TOK/8, blk256>>>(px, ln1g + i*DIM, ln1b + i*DIM,
                                           nullptr, pln16);
        gemm_mma<0><<<dim3(QKVD/128, TOK/128), blk256, GEMM_SMEM>>>(
            pln16, qkvt + (size_t)i*QKVD*DIM,
            nullptr, nullptr, pqkv, TOK, QKVD, DIM);
        attn_mma<<<dim3(SEQ/128, HEADS, BATCH), blk256, ATTN_SMEM>>>(pqkv, pct16);
        gemm_mma<3><<<dim3(DIM/128, TOK/128, 2), blk256, GEMM_SMEM>>>(
            pct16, outt + (size_t)i*DIM*INNER,
            nullptr, px, nullptr, TOK, DIM, INNER);

        ln_kernel<true><<<TOK/8, blk256>>>(px, ln2g + i*DIM, ln2b + i*DIM,
                                           nullptr, pln16);
        gemm_mma<1><<<dim3(MLPD/128, TOK/128), blk256, GEMM_SMEM>>>(
            pln16, w1t + (size_t)i*MLPD*DIM,
            b1 + (size_t)i*MLPD, nullptr, ph16, TOK, MLPD, DIM);
        gemm_mma<2><<<dim3(DIM/128, TOK/128, 2), blk256, GEMM_SMEM>>>(
            ph16, w2t + (size_t)i*DIM*MLPD,
            b2 + (size_t)i*DIM, px, nullptr, TOK, DIM, MLPD);
    }

    ln_kernel<false><<<TOK/8, blk256>>>(px, fng, fnb, (float*)d_out, nullptr);
}

// round 17
// speedup vs baseline: 1.0098x; 1.0098x over previous
#include <cuda_runtime.h>
#include <cuda_bf16.h>
#include <cuda_fp16.h>
#include <math.h>
#include <stdint.h>

#define DIM    768
#define DEPTH  6
#define HEADS  12
#define DHEAD  64
#define INNER  768
#define MLPD   3072
#define BATCH  4
#define SEQ    2048
#define TOK    (BATCH*SEQ)      /* 8192 */
#define QKVD   (3*INNER)        /* 2304 */
#define QSCALE 0.18033688011112042f   /* 0.125 * log2(e) */

// ---------------- scratch (device globals; no allocations) ----------------
__device__ float  g_x   [(size_t)TOK*DIM];    // residual stream fp32
__device__ __half g_qkv16[(size_t)TOK*QKVD];  // fused qkv fp16 (Q pre-scaled)
__device__ __half g_ln16[(size_t)TOK*DIM];    // LN output fp16
__device__ __half g_ct16[(size_t)TOK*DIM];    // attention ctx fp16
__device__ __half g_h16 [(size_t)TOK*MLPD];   // mlp hidden fp16
// transposed fp16 weights [layer][N][K]
__device__ __half g_wqkvt[(size_t)DEPTH*QKVD*DIM];
__device__ __half g_woutt[(size_t)DEPTH*DIM*INNER];
__device__ __half g_w1t  [(size_t)DEPTH*MLPD*DIM];
__device__ __half g_w2t  [(size_t)DEPTH*DIM*MLPD];

// ====================== PTX helpers =======================================
__device__ __forceinline__ uint32_t smem_u32(const void* p){
    uint32_t a;
    asm("{ .reg .u64 t; cvta.to.shared.u64 t, %1; cvt.u32.u64 %0, t; }"
        : "=r"(a) : "l"(p));
    return a;
}
__device__ __forceinline__ void cp16(uint32_t s, const void* g){
    asm volatile("cp.async.cg.shared.global [%0], [%1], 16;" :: "r"(s), "l"(g));
}
#define CP_COMMIT() asm volatile("cp.async.commit_group;" ::: "memory")
#define CP_WAIT1()  asm volatile("cp.async.wait_group 1;" ::: "memory")
#define CP_WAIT0()  asm volatile("cp.async.wait_group 0;" ::: "memory")

__device__ __forceinline__ void ldmx4(uint32_t addr, uint32_t& r0, uint32_t& r1,
                                      uint32_t& r2, uint32_t& r3){
    asm volatile("ldmatrix.sync.aligned.m8n8.x4.shared.b16 {%0,%1,%2,%3}, [%4];"
        : "=r"(r0), "=r"(r1), "=r"(r2), "=r"(r3) : "r"(addr));
}
__device__ __forceinline__ void ldmx4t(uint32_t addr, uint32_t& r0, uint32_t& r1,
                                       uint32_t& r2, uint32_t& r3){
    asm volatile("ldmatrix.sync.aligned.m8n8.x4.trans.shared.b16 {%0,%1,%2,%3}, [%4];"
        : "=r"(r0), "=r"(r1), "=r"(r2), "=r"(r3) : "r"(addr));
}
// fp16 mma
__device__ __forceinline__ void mma16816h(float* c, const uint32_t* a,
                                          uint32_t b0, uint32_t b1){
    asm volatile(
        "mma.sync.aligned.m16n8k16.row.col.f32.f16.f16.f32 "
        "{%0,%1,%2,%3}, {%4,%5,%6,%7}, {%8,%9}, {%0,%1,%2,%3};"
        : "+f"(c[0]), "+f"(c[1]), "+f"(c[2]), "+f"(c[3])
        : "r"(a[0]), "r"(a[1]), "r"(a[2]), "r"(a[3]), "r"(b0), "r"(b1));
}
// FMA-pipe exp2; degree-6 (accurate)
__device__ __forceinline__ float exp2_fast(float t){
    t = fmaxf(t, -120.f);
    float n = rintf(t);
    float f = t - n;
    float p = 1.5403530e-4f;
    p = fmaf(p, f, 1.3333558e-3f);
    p = fmaf(p, f, 9.6181291e-3f);
    p = fmaf(p, f, 5.5504109e-2f);
    p = fmaf(p, f, 2.4022651e-1f);
    p = fmaf(p, f, 6.9314718e-1f);
    p = fmaf(p, f, 1.0f);
    return __int_as_float(__float_as_int(p) + (((int)n) << 23));
}
// degree-4 exp2 for softmax probabilities (rel err ~4e-5)
__device__ __forceinline__ float exp2_p4(float t){
    t = fmaxf(t, -120.f);
    float n = rintf(t);
    float f = t - n;
    float p = 9.6181291e-3f;
    p = fmaf(p, f, 5.5504109e-2f);
    p = fmaf(p, f, 2.4022651e-1f);
    p = fmaf(p, f, 6.9314718e-1f);
    p = fmaf(p, f, 1.0f);
    return __int_as_float(__float_as_int(p) + (((int)n) << 23));
}

// ====================== weight transpose to fp16 ===========================
__global__ void transpose_cvt(const float* __restrict__ W,
                              __half* __restrict__ Wh, int K, int N)
{
    __shared__ float tile[32][33];
    const size_t off = (size_t)blockIdx.z * K * N;
    const int n0 = blockIdx.x * 32, k0 = blockIdx.y * 32;
    const int tx = threadIdx.x, ty = threadIdx.y;
#pragma unroll
    for (int i = 0; i < 32; i += 8)
        tile[ty + i][tx] = W[off + (size_t)(k0 + ty + i) * N + n0 + tx];
    __syncthreads();
#pragma unroll
    for (int i = 0; i < 32; i += 8) {
        size_t oidx = off + (size_t)(n0 + ty + i) * K + k0 + tx;
        Wh[oidx] = __float2half_rn(tile[tx][ty + i]);
    }
}

// ====================== LayerNorm: 1 warp / token, 8 tokens / block ========
template<bool HOUT>
__global__ void ln_kernel(const float* __restrict__ x, const float* __restrict__ g,
                          const float* __restrict__ b, float* __restrict__ y,
                          __half* __restrict__ yh)
{
    const int warp = threadIdx.x >> 5, lane = threadIdx.x & 31;
    const int t = blockIdx.x * 8 + warp;
    const float* xp = x + (size_t)t * DIM;

    float v[24];
    float s1 = 0.f, s2 = 0.f;
#pragma unroll
    for (int i = 0; i < 6; i++) {
        float4 f = *reinterpret_cast<const float4*>(xp + i * 128 + lane * 4);
        v[i*4+0] = f.x; v[i*4+1] = f.y; v[i*4+2] = f.z; v[i*4+3] = f.w;
        s1 += f.x + f.y + f.z + f.w;
        s2 += f.x*f.x + f.y*f.y + f.z*f.z + f.w*f.w;
    }
#pragma unroll
    for (int o = 16; o > 0; o >>= 1) {
        s1 += __shfl_xor_sync(0xffffffffu, s1, o);
        s2 += __shfl_xor_sync(0xffffffffu, s2, o);
    }
    const float mu  = s1 * (1.f / DIM);
    const float var = s2 * (1.f / DIM) - mu * mu;
    const float rs  = rsqrtf(var + 1e-5f);

#pragma unroll
    for (int i = 0; i < 6; i++) {
        const int d = i * 128 + lane * 4;
        float4 gg = *reinterpret_cast<const float4*>(g + d);
        float4 bb = *reinterpret_cast<const float4*>(b + d);
        float y0 = (v[i*4+0] - mu) * rs * gg.x + bb.x;
        float y1 = (v[i*4+1] - mu) * rs * gg.y + bb.y;
        float y2 = (v[i*4+2] - mu) * rs * gg.z + bb.z;
        float y3 = (v[i*4+3] - mu) * rs * gg.w + bb.w;
        if (HOUT) {
            uint2 pk;
            __half h0 = __float2half_rn(y0), h1 = __float2half_rn(y1);
            __half h2 = __float2half_rn(y2), h3 = __float2half_rn(y3);
            pk.x = (uint32_t)__half_as_ushort(h0) | ((uint32_t)__half_as_ushort(h1) << 16);
            pk.y = (uint32_t)__half_as_ushort(h2) | ((uint32_t)__half_as_ushort(h3) << 16);
            *reinterpret_cast<uint2*>(yh + (size_t)t * DIM + d) = pk;
        } else {
            *reinterpret_cast<float4*>(y + (size_t)t * DIM + d) =
                make_float4(y0, y1, y2, y3);
        }
    }
}

// ====================== fp16 1-product GEMM (BK=64, 3-stage, 2 CTAs/SM) ====
// Split-K via gridDim.z.  EPI: 0 = qkv out; 1 = +bias,gelu,fp16;
// 2 = +bias(z0) atomic += xres; 3 = atomic += xres.
#define STAGE_SZ 32768u
template<int EPI>
__global__ void __launch_bounds__(256, 2)
gemm_mma(const __half* __restrict__ Ah, const __half* __restrict__ Bh,
         const float* __restrict__ bias, float* __restrict__ xres,
         __half* __restrict__ Ch, int M, int N, int K)
{
    extern __shared__ char smem[];
    const uint32_t sb0 = smem_u32(smem);
    const int tid  = threadIdx.x;
    const int lane = tid & 31, warp = tid >> 5;
    const int wm = warp >> 1, wn = warp & 1;
    const int bn = blockIdx.x, bm = blockIdx.y;
    const int ksp   = K / (int)gridDim.z;
    const int kbase = blockIdx.z * ksp;
    const int nkt   = ksp >> 6;

    auto load_stage = [&](int kt, int st){
        const uint32_t base = sb0 + (uint32_t)st * STAGE_SZ;
        const size_t kof = (size_t)kbase + (size_t)kt * 64;
#pragma unroll
        for (int i = 0; i < 4; i++) {
            const int idx = tid + i * 256;
            const int row = idx >> 3, c = idx & 7;
            const uint32_t so = (uint32_t)(row * 128 + ((c ^ (row & 7)) << 4));
            const size_t ga = (size_t)(bm * 128 + row) * K + kof + c * 8;
            const size_t gb = (size_t)(bn * 128 + row) * K + kof + c * 8;
            cp16(base + so,          Ah + ga);
            cp16(base + 16384u + so, Bh + gb);
        }
    };

    float acc[2][8][4];
#pragma unroll
    for (int mt = 0; mt < 2; mt++)
#pragma unroll
        for (int nt = 0; nt < 8; nt++)
#pragma unroll
            for (int q = 0; q < 4; q++) acc[mt][nt][q] = 0.f;

    load_stage(0, 0); CP_COMMIT();
    load_stage(1, 1); CP_COMMIT();

    const int arow = wm * 32 + (lane & 15);
    const int acs  = lane >> 4;
    const int brow = wn * 64 + (lane & 7) + ((lane >> 4) << 3);
    const int bcs  = (lane >> 3) & 1;

    for (int kt = 0; kt < nkt; kt++) {
        if (kt == nkt - 1) { CP_WAIT0(); } else { CP_WAIT1(); }
        __syncthreads();
        if (kt + 2 < nkt) { load_stage(kt + 2, (kt + 2) % 3); CP_COMMIT(); }

        const uint32_t base = sb0 + (uint32_t)(kt % 3) * STAGE_SZ;
#pragma unroll
        for (int ks = 0; ks < 4; ks++) {
            uint32_t ah[2][4];
#pragma unroll
            for (int mt = 0; mt < 2; mt++) {
                const int r = arow + mt * 16;
                const int c = ks * 2 + acs;
                const uint32_t off = (uint32_t)(r * 128 + ((c ^ (r & 7)) << 4));
                ldmx4(base + off, ah[mt][0], ah[mt][1], ah[mt][2], ah[mt][3]);
            }
#pragma unroll
            for (int bt = 0; bt < 4; bt++) {
                const int r = brow + bt * 16;
                const int c = ks * 2 + bcs;
                const uint32_t off = (uint32_t)(r * 128 + ((c ^ (r & 7)) << 4));
                uint32_t bh[4];
                ldmx4(base + 16384u + off, bh[0], bh[1], bh[2], bh[3]);
#pragma unroll
                for (int mt = 0; mt < 2; mt++) {
                    mma16816h(acc[mt][2*bt],   ah[mt], bh[0], bh[1]);
                    mma16816h(acc[mt][2*bt+1], ah[mt], bh[2], bh[3]);
                }
            }
        }
        __syncthreads();
    }

    const int rbase = bm * 128 + wm * 32 + (lane >> 2);
    const int cbase = bn * 128 + wn * 64 + (lane & 3) * 2;
    const bool z0 = (blockIdx.z == 0);
#pragma unroll
    for (int mt = 0; mt < 2; mt++) {
#pragma unroll
        for (int nt = 0; nt < 8; nt++) {
            const int gcol = cbase + nt * 8;
#pragma unroll
            for (int h = 0; h < 2; h++) {
                const int grow = rbase + mt * 16 + h * 8;
                float v0 = acc[mt][nt][2*h], v1 = acc[mt][nt][2*h+1];
                const size_t oidx = (size_t)grow * N + gcol;
                if (EPI == 0 || EPI == 1) {
                    if (EPI == 0) {
                        const float sc = (gcol < INNER) ? QSCALE : 1.f;
                        v0 *= sc; v1 *= sc;
                    } else {
                        v0 += bias[gcol];     v1 += bias[gcol + 1];
                        v0 = 0.5f * v0 * (1.f + erff(v0 * 0.70710678118654752f));
                        v1 = 0.5f * v1 * (1.f + erff(v1 * 0.70710678118654752f));
                    }
                    __half h0 = __float2half_rn(v0), h1 = __float2half_rn(v1);
                    *reinterpret_cast<uint32_t*>(Ch + oidx) =
                        (uint32_t)__half_as_ushort(h0) |
                        ((uint32_t)__half_as_ushort(h1) << 16);
                } else {
                    if (EPI == 2 && z0) { v0 += bias[gcol]; v1 += bias[gcol + 1]; }
                    atomicAdd(xres + oidx,     v0);
                    atomicAdd(xres + oidx + 1, v1);
                }
            }
        }
    }
}

// ====================== fp16 1-product flash attention (2 CTAs/SM) =========
// grid (SEQ/128, HEADS, BATCH), 256 threads (8 warps x 16 query rows).
#define ATTN_SMEM (16384 + 2*16384)
__global__ void __launch_bounds__(256, 2)
attn_mma(const __half* __restrict__ qkv, __half* __restrict__ ctx)
{
    extern __shared__ char smem[];
    const uint32_t sb = smem_u32(smem);
    const uint32_t QS = sb;
    const int tid = threadIdx.x, lane = tid & 31, wid = tid >> 5;
    const int b = blockIdx.z, h = blockIdx.y, qt = blockIdx.x;
    const int tok0 = b * SEQ + qt * 128;

#pragma unroll
    for (int i = 0; i < 4; i++) {
        const int idx = tid + i * 256;
        const int row = idx >> 3, c = idx & 7;
        const uint32_t so = (uint32_t)(row * 128 + ((c ^ (row & 7)) << 4));
        cp16(QS + so, qkv + (size_t)(tok0 + row) * QKVD + h * DHEAD + c * 8);
    }

    auto load_kv = [&](int t, int st){
        const uint32_t base = sb + 16384u + (uint32_t)st * 16384u;
        const int kv0 = b * SEQ + t * 64;
#pragma unroll
        for (int i = 0; i < 2; i++) {
            const int idx = tid + i * 256;
            const int row = idx >> 3, c = idx & 7;
            const uint32_t so = (uint32_t)(row * 128 + ((c ^ (row & 7)) << 4));
            const size_t gk = (size_t)(kv0 + row) * QKVD + INNER + h * DHEAD + c * 8;
            const size_t gv = (size_t)(kv0 + row) * QKVD + 2 * INNER + h * DHEAD + c * 8;
            cp16(base + so,         qkv + gk);
            cp16(base + 8192u + so, qkv + gv);
        }
    };
    load_kv(0, 0); CP_COMMIT();

    float O[8][4];
#pragma unroll
    for (int nt = 0; nt < 8; nt++)
#pragma unroll
        for (int q = 0; q < 4; q++) O[nt][q] = 0.f;
    float m0 = -1e30f, m1 = -1e30f, l0 = 0.f, l1 = 0.f;
    const int m0row = wid * 16;

    const int NT = SEQ / 64;
    for (int t = 0; t < NT; t++) {
        if (t + 1 < NT) { load_kv(t + 1, (t + 1) & 1); CP_COMMIT(); CP_WAIT1(); }
        else            { CP_WAIT0(); }
        __syncthreads();
        const uint32_t kb = sb + 16384u + (uint32_t)(t & 1) * 16384u;

        float S[8][4];
#pragma unroll
        for (int nt = 0; nt < 8; nt++)
#pragma unroll
            for (int q = 0; q < 4; q++) S[nt][q] = 0.f;
#pragma unroll
        for (int ks = 0; ks < 4; ks++) {
            uint32_t qf[4];
            {
                const int r = m0row + (lane & 15);
                const int c = ks * 2 + (lane >> 4);
                const uint32_t off = (uint32_t)(r * 128 + ((c ^ (r & 7)) << 4));
                ldmx4(QS + off, qf[0], qf[1], qf[2], qf[3]);
            }
#pragma unroll
            for (int bt = 0; bt < 4; bt++) {
                const int r = bt * 16 + (lane & 7) + ((lane >> 4) << 3);
                const int c = ks * 2 + ((lane >> 3) & 1);
                const uint32_t off = (uint32_t)(r * 128 + ((c ^ (r & 7)) << 4));
                uint32_t kh[4];
                ldmx4(kb + off, kh[0], kh[1], kh[2], kh[3]);
                mma16816h(S[2*bt],   qf, kh[0], kh[1]);
                mma16816h(S[2*bt+1], qf, kh[2], kh[3]);
            }
        }

        // ---- online softmax with skip-rescale ----
        float mt0 = -1e30f, mt1 = -1e30f;
#pragma unroll
        for (int nt = 0; nt < 8; nt++) {
            mt0 = fmaxf(mt0, fmaxf(S[nt][0], S[nt][1]));
            mt1 = fmaxf(mt1, fmaxf(S[nt][2], S[nt][3]));
        }
        mt0 = fmaxf(mt0, __shfl_xor_sync(0xffffffffu, mt0, 1));
        mt0 = fmaxf(mt0, __shfl_xor_sync(0xffffffffu, mt0, 2));
        mt1 = fmaxf(mt1, __shfl_xor_sync(0xffffffffu, mt1, 1));
        mt1 = fmaxf(mt1, __shfl_xor_sync(0xffffffffu, mt1, 2));

        const bool chg = __any_sync(0xffffffffu, (mt0 > m0) | (mt1 > m1));
        if (chg) {
            const float mn0 = fmaxf(m0, mt0), mn1 = fmaxf(m1, mt1);
            const float cr0 = exp2_fast(m0 - mn0), cr1 = exp2_fast(m1 - mn1);
            m0 = mn0; m1 = mn1;
            l0 *= cr0; l1 *= cr1;
#pragma unroll
            for (int nt = 0; nt < 8; nt++) {
                O[nt][0] *= cr0; O[nt][1] *= cr0;
                O[nt][2] *= cr1; O[nt][3] *= cr1;
            }
        }

        uint32_t phi[4][4];
        float s0 = 0.f, s1 = 0.f;
#pragma unroll
        for (int nt = 0; nt < 8; nt++) {
            float p0 = exp2_p4(S[nt][0] - m0);
            float p1 = exp2_p4(S[nt][1] - m0);
            float p2 = exp2_p4(S[nt][2] - m1);
            float p3 = exp2_p4(S[nt][3] - m1);
            s0 += p0 + p1; s1 += p2 + p3;
            __half h0 = __float2half_rn(p0), h1 = __float2half_rn(p1);
            __half h2 = __float2half_rn(p2), h3 = __float2half_rn(p3);
            const int t2 = nt >> 1, o = (nt & 1) * 2;
            phi[t2][o] = (uint32_t)__half_as_ushort(h0) |
                         ((uint32_t)__half_as_ushort(h1) << 16);
            phi[t2][o+1] = (uint32_t)__half_as_ushort(h2) |
                           ((uint32_t)__half_as_ushort(h3) << 16);
        }
        s0 += __shfl_xor_sync(0xffffffffu, s0, 1);
        s0 += __shfl_xor_sync(0xffffffffu, s0, 2);
        s1 += __shfl_xor_sync(0xffffffffu, s1, 1);
        s1 += __shfl_xor_sync(0xffffffffu, s1, 2);
        l0 += s0;
        l1 += s1;

#pragma unroll
        for (int t2 = 0; t2 < 4; t2++) {
#pragma unroll
            for (int dn = 0; dn < 4; dn++) {
                const int r = t2 * 16 + (lane & 15);
                const int c = dn * 2 + (lane >> 4);
                const uint32_t off = (uint32_t)(r * 128 + ((c ^ (r & 7)) << 4));
                uint32_t vh[4];
                ldmx4t(kb + 8192u + off, vh[0], vh[1], vh[2], vh[3]);
                mma16816h(O[2*dn],   phi[t2], vh[0], vh[1]);
                mma16816h(O[2*dn+1], phi[t2], vh[2], vh[3]);
            }
        }
        __syncthreads();
    }

    const float i0 = 1.f / l0, i1 = 1.f / l1;
    const int r0 = tok0 + m0row + (lane >> 2);
#pragma unroll
    for (int nt = 0; nt < 8; nt++) {
        const int col = h * DHEAD + nt * 8 + (lane & 3) * 2;
#pragma unroll
        for (int hh = 0; hh < 2; hh++) {
            const float inv = hh ? i1 : i0;
            float v0 = O[nt][2*hh] * inv, v1 = O[nt][2*hh+1] * inv;
            __half h0 = __float2half_rn(v0), h1 = __float2half_rn(v1);
            const size_t oidx = (size_t)(r0 + hh * 8) * DIM + col;
            *reinterpret_cast<uint32_t*>(ctx + oidx) =
                (uint32_t)__half_as_ushort(h0) |
                ((uint32_t)__half_as_ushort(h1) << 16);
        }
    }
}

// ====================== driver =============================================
#define GEMM_SMEM (3 * 32768)

extern "C" void kernel_launch(void* const* d_in, const int* in_sizes, int n_in,
                              void* d_out, int out_size)
{
    const float* x    = (const float*)d_in[0];
    const float* ln1g = (const float*)d_in[1];
    const float* ln1b = (const float*)d_in[2];
    const float* wqkv = (const float*)d_in[3];
    const float* wout = (const float*)d_in[4];
    const float* ln2g = (const float*)d_in[5];
    const float* ln2b = (const float*)d_in[6];
    const float* w1   = (const float*)d_in[7];
    const float* b1   = (const float*)d_in[8];
    const float* w2   = (const float*)d_in[9];
    const float* b2   = (const float*)d_in[10];
    const float* fng  = (const float*)d_in[11];
    const float* fnb  = (const float*)d_in[12];

    float *px;
    __half *pqkv, *pln16, *pct16, *ph16;
    __half *qkvt, *outt, *w1t, *w2t;
    cudaGetSymbolAddress((void**)&px,    g_x);
    cudaGetSymbolAddress((void**)&pqkv,  g_qkv16);
    cudaGetSymbolAddress((void**)&pln16, g_ln16);
    cudaGetSymbolAddress((void**)&pct16, g_ct16);
    cudaGetSymbolAddress((void**)&ph16,  g_h16);
    cudaGetSymbolAddress((void**)&qkvt,  g_wqkvt);
    cudaGetSymbolAddress((void**)&outt,  g_woutt);
    cudaGetSymbolAddress((void**)&w1t,   g_w1t);
    cudaGetSymbolAddress((void**)&w2t,   g_w2t);

    cudaFuncSetAttribute(gemm_mma<0>, cudaFuncAttributeMaxDynamicSharedMemorySize, GEMM_SMEM);
    cudaFuncSetAttribute(gemm_mma<1>, cudaFuncAttributeMaxDynamicSharedMemorySize, GEMM_SMEM);
    cudaFuncSetAttribute(gemm_mma<2>, cudaFuncAttributeMaxDynamicSharedMemorySize, GEMM_SMEM);
    cudaFuncSetAttribute(gemm_mma<3>, cudaFuncAttributeMaxDynamicSharedMemorySize, GEMM_SMEM);
    cudaFuncSetAttribute(attn_mma, cudaFuncAttributeMaxDynamicSharedMemorySize, ATTN_SMEM);

    {
        dim3 tblk(32, 8);
        transpose_cvt<<<dim3(QKVD/32, DIM/32, DEPTH), tblk>>>(wqkv, qkvt, DIM, QKVD);
        transpose_cvt<<<dim3(DIM/32, INNER/32, DEPTH), tblk>>>(wout, outt, INNER, DIM);
        transpose_cvt<<<dim3(MLPD/32, DIM/32, DEPTH), tblk>>>(w1, w1t, DIM, MLPD);
        transpose_cvt<<<dim3(DIM/32, MLPD/32, DEPTH), tblk>>>(w2, w2t, MLPD, DIM);
    }

    cudaMemcpyAsync(px, x, sizeof(float) * (size_t)TOK * DIM,
                    cudaMemcpyDeviceToDevice, 0);

    const dim3 blk256(256);
    for (int i = 0; i < DEPTH; i++) {
        ln_kernel<true><<<TOK/8, blk256>>>(px, ln1g + i*DIM, ln1b + i*DIM,
                                           nullptr, pln16);
        gemm_mma<0><<<dim3(QKVD/128, TOK/128), blk256, GEMM_SMEM>>>(
            pln16, qkvt + (size_t)i*QKVD*DIM,
            nullptr, nullptr, pqkv, TOK, QKVD, DIM);
        attn_mma<<<dim3(SEQ/128, HEADS, BATCH), blk256, ATTN_SMEM>>>(pqkv, pct16);
        gemm_mma<3><<<dim3(DIM/128, TOK/128, 3), blk256, GEMM_SMEM>>>(
            pct16, outt + (size_t)i*DIM*INNER,
            nullptr, px, nullptr, TOK, DIM, INNER);

        ln_kernel<true><<<TOK/8, blk256>>>(px, ln2g + i*DIM, ln2b + i*DIM,
                                           nullptr, pln16);
        gemm_mma<1><<<dim3(MLPD/128, TOK/128), blk256, GEMM_SMEM>>>(
            pln16, w1t + (size_t)i*MLPD*DIM,
            b1 + (size_t)i*MLPD, nullptr, ph16, TOK, MLPD, DIM);
        gemm_mma<2><<<dim3(DIM/128, TOK/128, 3), blk256, GEMM_SMEM>>>(
            ph16, w2t + (size_t)i*DIM*MLPD,
            b2 + (size_t)i*DIM, px, nullptr, TOK, DIM, MLPD);
    }

    ln_kernel<false><<<TOK/8, blk256>>>(px, fng, fnb, (float*)d_out, nullptr);
}